// round 2
// baseline (speedup 1.0000x reference)
#include <cuda_runtime.h>

// B-spline layer via per-interval cubic polynomials with control points folded in.
//
// u = 55*x - ii, ii = floor(55x) in [0,54].
// out[b,f] = q0[ii,f] + q1[ii,f]*u + q2[ii,f]*u^2 + q3[ii,f]*u^3 + bias[f]
// where q_d[ii,f] = sum_r coef(ii,r,d) * C[ii+3+r, f], and coef are the
// degree-3 Cox-de Boor basis polynomial coefficients (in local coord u)
// on interval ii, computed in double by a tiny precompute kernel.

#define NF 256
#define NBATCH 4096
#define NII 55
#define ROWS_PER_BLOCK 128

// [ftile 8][ii 55][lane 32] -> float4 (q0,q1,q2,q3). 225 KB, L2-resident.
__device__ float4 g_tab[8 * NII * 32];

// Extended knots (double, exact per reference construction), idx in [3,64]:
//   idx 3..5  : -0.002 + 0.0005*(idx-3)
//   idx 6..61 : (idx-6)/55
//   idx 62..64: 1.001 + 0.0005*(idx-62)
__device__ __forceinline__ double knotD(int idx) {
    if (idx < 6)  return -0.002 + 0.0005 * (double)(idx - 3);
    if (idx > 61) return 1.001  + 0.0005 * (double)(idx - 62);
    return (double)(idx - 6) / 55.0;
}

__global__ void BSL_precompute(const float* __restrict__ C) {
    const int ii = blockIdx.x;      // interval 0..54
    const int f  = threadIdx.x;     // feature 0..255
    const int j  = ii + 6;          // knot span [t_j, t_{j+1})

    // Cox-de Boor on polynomial coefficients in u, where x = (ii + u)/55.
    // After step k: P[r] = B^k_{j-k+r}(u), r = 0..k, coeffs P[r][d] for u^d.
    double P[4][4] = {};
    P[0][0] = 1.0;
    const double x0 = (double)ii / 55.0;   // constant part of x
    const double bs = 1.0 / 55.0;          // du/dx^-1 part: x = x0 + bs*u

    #pragma unroll
    for (int k = 1; k <= 3; ++k) {
        double Q[4][4] = {};
        #pragma unroll
        for (int r = 0; r <= 3; ++r) {
            if (r > k) continue;
            const int i = j - k + r;
            if (r >= 1) {   // (x - t_i)/(t_{i+k}-t_i) * B^{k-1}_i  (= old P[r-1])
                const double inv = 1.0 / (knotD(i + k) - knotD(i));
                const double a = (x0 - knotD(i)) * inv;
                const double b = bs * inv;
                #pragma unroll
                for (int d = 0; d < 4; ++d) {
                    Q[r][d] += a * P[r - 1][d];
                    if (d > 0) Q[r][d] += b * P[r - 1][d - 1];
                }
            }
            if (r <= k - 1) {   // (t_{i+k+1} - x)/(t_{i+k+1}-t_{i+1}) * B^{k-1}_{i+1} (= old P[r])
                const double inv = 1.0 / (knotD(i + k + 1) - knotD(i + 1));
                const double a = (knotD(i + k + 1) - x0) * inv;
                const double b = -bs * inv;
                #pragma unroll
                for (int d = 0; d < 4; ++d) {
                    Q[r][d] += a * P[r][d];
                    if (d > 0) Q[r][d] += b * P[r][d - 1];
                }
            }
        }
        #pragma unroll
        for (int r = 0; r < 4; ++r)
            #pragma unroll
            for (int d = 0; d < 4; ++d) P[r][d] = Q[r][d];
    }

    // Fold basis polys with control points: q_d = sum_r P[r][d] * C[ii+3+r, f]
    double q[4] = {0.0, 0.0, 0.0, 0.0};
    #pragma unroll
    for (int r = 0; r < 4; ++r) {
        const double c = (double)C[(ii + 3 + r) * NF + f];
        #pragma unroll
        for (int d = 0; d < 4; ++d) q[d] += P[r][d] * c;
    }

    const int tile = f >> 5, lane = f & 31;
    g_tab[(tile * NII + ii) * 32 + lane] =
        make_float4((float)q[0], (float)q[1], (float)q[2], (float)q[3]);
}

__global__ __launch_bounds__(256) void BSL_25898652795515_kernel(
    const float* __restrict__ X,      // (4096, 256)
    const float* __restrict__ bias,   // (256,)
    float* __restrict__ out)          // (4096, 256)
{
    __shared__ float4 sT[NII * 32];   // 28160 B coefficient tile

    const int tile = blockIdx.y;
    const int row0 = blockIdx.x * ROWS_PER_BLOCK;
    const int tid  = threadIdx.x;

    #pragma unroll
    for (int idx = tid; idx < NII * 32; idx += 256)
        sT[idx] = g_tab[tile * (NII * 32) + idx];
    __syncthreads();

    const int lane = tid & 31;
    const int wrp  = tid >> 5;
    const int f    = tile * 32 + lane;
    const float bf = bias[f];

    #pragma unroll
    for (int it = 0; it < ROWS_PER_BLOCK / 8; ++it) {
        const int b = row0 + it * 8 + wrp;
        const float x  = X[b * NF + f];
        const float xs = x * 55.0f;
        int ii = (int)xs;                 // x >= 0, trunc == floor
        ii = min(ii, 54);
        const float u = xs - (float)ii;
        // conflict-free LDS.128: ii stride is 512 B (multiple of 32 banks)
        const float4 c = sT[ii * 32 + lane];
        const float q = fmaf(fmaf(fmaf(c.w, u, c.z), u, c.y), u, c.x);
        out[b * NF + f] = q + bf;
    }
}

extern "C" void kernel_launch(void* const* d_in, const int* in_sizes, int n_in,
                              void* d_out, int out_size) {
    const float* x    = (const float*)d_in[0];   // (4096, 256)
    const float* ctrl = (const float*)d_in[1];   // (64, 256)
    const float* bias = (const float*)d_in[2];   // (256,)
    float* out = (float*)d_out;

    BSL_precompute<<<NII, NF>>>(ctrl);

    dim3 grid(NBATCH / ROWS_PER_BLOCK, NF / 32);   // (32, 8)
    BSL_25898652795515_kernel<<<grid, 256>>>(x, bias, out);
}

// round 3
// speedup vs baseline: 4.8821x; 4.8821x over previous
#include <cuda_runtime.h>

// B-spline layer: per-interval cubic polynomial with control points folded in,
// single fused kernel. The interval-local basis polynomial coefficients
// P[ii][r][d]  (B_{ii+3+r}(x) = sum_d P[ii][r][d] * u^d on interval ii,
// u = 55x - ii) depend only on the knot vector -> computed on the HOST in
// double and passed by value in the const bank (3.5 KB).

#define NF 256
#define NBATCH 4096
#define NII 55
#define NK 64
#define ROWS_PER_BLOCK 64

struct PTab { float p[NII][4][4]; };

// ---------------- host-side knot/coefficient math (double) ----------------
static double knotD_h(int idx) {
    if (idx < 6)  return -0.002 + 0.0005 * (double)(idx - 3);
    if (idx > 61) return 1.001  + 0.0005 * (double)(idx - 62);
    return (double)(idx - 6) / 55.0;
}

static void make_ptab(PTab& T) {
    for (int ii = 0; ii < NII; ++ii) {
        const int j = ii + 6;
        double P[4][4] = {};
        P[0][0] = 1.0;
        const double x0 = (double)ii / 55.0;
        const double bs = 1.0 / 55.0;   // x = x0 + bs*u
        for (int k = 1; k <= 3; ++k) {
            double Q[4][4] = {};
            for (int r = 0; r <= k; ++r) {
                const int i = j - k + r;
                if (r >= 1) {
                    const double inv = 1.0 / (knotD_h(i + k) - knotD_h(i));
                    const double a = (x0 - knotD_h(i)) * inv;
                    const double b = bs * inv;
                    for (int d = 0; d < 4; ++d) {
                        Q[r][d] += a * P[r - 1][d];
                        if (d > 0) Q[r][d] += b * P[r - 1][d - 1];
                    }
                }
                if (r <= k - 1) {
                    const double inv = 1.0 / (knotD_h(i + k + 1) - knotD_h(i + 1));
                    const double a = (knotD_h(i + k + 1) - x0) * inv;
                    const double b = -bs * inv;
                    for (int d = 0; d < 4; ++d) {
                        Q[r][d] += a * P[r][d];
                        if (d > 0) Q[r][d] += b * P[r][d - 1];
                    }
                }
            }
            for (int r = 0; r < 4; ++r)
                for (int d = 0; d < 4; ++d) P[r][d] = Q[r][d];
        }
        for (int r = 0; r < 4; ++r)
            for (int d = 0; d < 4; ++d) T.p[ii][r][d] = (float)P[r][d];
    }
}

// --------------------------------- kernel ---------------------------------
__global__ __launch_bounds__(256) void BSL_25898652795515_kernel(
    const PTab T,                     // 3.5 KB in const bank
    const float* __restrict__ X,      // (4096, 256)
    const float* __restrict__ C,      // (64, 256)
    const float* __restrict__ bias,   // (256,)
    float* __restrict__ out)          // (4096, 256)
{
    __shared__ float  sC[NK * 32];        // 8 KB control tile
    __shared__ float4 sT[NII * 32];       // 28 KB folded coefficient tile

    const int tile = blockIdx.y;          // feature tile (32 features)
    const int f0   = tile * 32;
    const int row0 = blockIdx.x * ROWS_PER_BLOCK;
    const int tid  = threadIdx.x;
    const int lane = tid & 31;
    const int wrp  = tid >> 5;

    // Load control tile: sC[k*32 + c] = C[k*256 + f0 + c]
    #pragma unroll
    for (int idx = tid; idx < NK * 32; idx += 256)
        sC[idx] = C[(idx >> 5) * NF + f0 + (idx & 31)];
    __syncthreads();

    // Fold: sT[ii*32 + lane].d = sum_r P[ii][r][d] * sC[(ii+3+r)*32 + lane]
    // Warp-uniform ii per iteration (o>>5 == wrp + 8*iter): P reads uniform,
    // sC reads conflict-free (bank == lane).
    #pragma unroll
    for (int o = tid; o < NII * 32; o += 256) {
        const int ii = o >> 5;
        const int ln = o & 31;
        const float c0 = sC[(ii + 3) * 32 + ln];
        const float c1 = sC[(ii + 4) * 32 + ln];
        const float c2 = sC[(ii + 5) * 32 + ln];
        const float c3 = sC[(ii + 6) * 32 + ln];
        float4 q;
        q.x = T.p[ii][0][0]*c0 + T.p[ii][1][0]*c1 + T.p[ii][2][0]*c2 + T.p[ii][3][0]*c3;
        q.y = T.p[ii][0][1]*c0 + T.p[ii][1][1]*c1 + T.p[ii][2][1]*c2 + T.p[ii][3][1]*c3;
        q.z = T.p[ii][0][2]*c0 + T.p[ii][1][2]*c1 + T.p[ii][2][2]*c2 + T.p[ii][3][2]*c3;
        q.w = T.p[ii][0][3]*c0 + T.p[ii][1][3]*c1 + T.p[ii][2][3]*c2 + T.p[ii][3][3]*c3;
        sT[o] = q;
    }
    __syncthreads();

    const int f   = f0 + lane;
    const float bf = bias[f];

    #pragma unroll
    for (int it = 0; it < ROWS_PER_BLOCK / 8; ++it) {
        const int b = row0 + it * 8 + wrp;
        const float x  = X[b * NF + f];
        const float xs = x * 55.0f;
        int ii = (int)xs;                 // x >= 0 -> trunc == floor
        ii = min(ii, 54);
        const float u = xs - (float)ii;
        // conflict-free LDS.128: ii stride = 512 B (multiple of 32 banks)
        const float4 c = sT[ii * 32 + lane];
        const float q = fmaf(fmaf(fmaf(c.w, u, c.z), u, c.y), u, c.x);
        out[b * NF + f] = q + bf;
    }
}

extern "C" void kernel_launch(void* const* d_in, const int* in_sizes, int n_in,
                              void* d_out, int out_size) {
    const float* x    = (const float*)d_in[0];   // (4096, 256)
    const float* ctrl = (const float*)d_in[1];   // (64, 256)
    const float* bias = (const float*)d_in[2];   // (256,)
    float* out = (float*)d_out;

    PTab T;
    make_ptab(T);   // host double math, knot-only, deterministic

    dim3 grid(NBATCH / ROWS_PER_BLOCK, NF / 32);   // (64, 8) = 512 blocks
    BSL_25898652795515_kernel<<<grid, 256>>>(T, x, ctrl, bias, out);
}

// round 4
// speedup vs baseline: 4.8996x; 1.0036x over previous
#include <cuda_runtime.h>

// B-spline layer, two kernels:
//  K1 (fold): q[ii][f][0..3] = sum_r P[ii][r][d] * C[ii+3+r, f]  (+bias in q0)
//     P = degree-3 Cox-de Boor basis polynomial coefficients in local coord
//     u = 55x - ii, computed on the HOST in double (knot-only, deterministic),
//     passed by value in the const bank (3.5 KB).
//  K2 (main): out[b,f] = ((q3*u + q2)*u + q1)*u + q0   via one LDS.128.

#define NF 256
#define NBATCH 4096
#define NII 55
#define ROWS_PER_BLOCK 64
#define K2_THREADS 512

struct PTab { float p[NII][4][4]; };

// [tile 8][ii 55][lane 32] float4 (q0+bias, q1, q2, q3) — 225 KB, L2-resident.
__device__ float4 g_tab[8 * NII * 32];

// ---------------- host-side knot/coefficient math (double) ----------------
static double knotD_h(int idx) {
    if (idx < 6)  return -0.002 + 0.0005 * (double)(idx - 3);
    if (idx > 61) return 1.001  + 0.0005 * (double)(idx - 62);
    return (double)(idx - 6) / 55.0;
}

static void make_ptab(PTab& T) {
    for (int ii = 0; ii < NII; ++ii) {
        const int j = ii + 6;
        double P[4][4] = {};
        P[0][0] = 1.0;
        const double x0 = (double)ii / 55.0;
        const double bs = 1.0 / 55.0;   // x = x0 + bs*u
        for (int k = 1; k <= 3; ++k) {
            double Q[4][4] = {};
            for (int r = 0; r <= k; ++r) {
                const int i = j - k + r;
                if (r >= 1) {
                    const double inv = 1.0 / (knotD_h(i + k) - knotD_h(i));
                    const double a = (x0 - knotD_h(i)) * inv;
                    const double b = bs * inv;
                    for (int d = 0; d < 4; ++d) {
                        Q[r][d] += a * P[r - 1][d];
                        if (d > 0) Q[r][d] += b * P[r - 1][d - 1];
                    }
                }
                if (r <= k - 1) {
                    const double inv = 1.0 / (knotD_h(i + k + 1) - knotD_h(i + 1));
                    const double a = (knotD_h(i + k + 1) - x0) * inv;
                    const double b = -bs * inv;
                    for (int d = 0; d < 4; ++d) {
                        Q[r][d] += a * P[r][d];
                        if (d > 0) Q[r][d] += b * P[r][d - 1];
                    }
                }
            }
            for (int r = 0; r < 4; ++r)
                for (int d = 0; d < 4; ++d) P[r][d] = Q[r][d];
        }
        for (int r = 0; r < 4; ++r)
            for (int d = 0; d < 4; ++d) T.p[ii][r][d] = (float)P[r][d];
    }
}

// ------------------------------ K1: fold -----------------------------------
__global__ __launch_bounds__(256) void BSL_fold(
    const PTab T,
    const float* __restrict__ C,      // (64, 256)
    const float* __restrict__ bias)   // (256,)
{
    const int ii = blockIdx.x;        // 0..54 (warp-uniform -> P reads = LDC)
    const int f  = threadIdx.x;       // 0..255
    const float c0 = C[(ii + 3) * NF + f];
    const float c1 = C[(ii + 4) * NF + f];
    const float c2 = C[(ii + 5) * NF + f];
    const float c3 = C[(ii + 6) * NF + f];
    float4 q;
    q.x = T.p[ii][0][0]*c0 + T.p[ii][1][0]*c1 + T.p[ii][2][0]*c2 + T.p[ii][3][0]*c3
        + bias[f];
    q.y = T.p[ii][0][1]*c0 + T.p[ii][1][1]*c1 + T.p[ii][2][1]*c2 + T.p[ii][3][1]*c3;
    q.z = T.p[ii][0][2]*c0 + T.p[ii][1][2]*c1 + T.p[ii][2][2]*c2 + T.p[ii][3][2]*c3;
    q.w = T.p[ii][0][3]*c0 + T.p[ii][1][3]*c1 + T.p[ii][2][3]*c2 + T.p[ii][3][3]*c3;
    g_tab[((f >> 5) * NII + ii) * 32 + (f & 31)] = q;
}

// ------------------------------ K2: main -----------------------------------
__global__ __launch_bounds__(K2_THREADS) void BSL_25898652795515_kernel(
    const float* __restrict__ X,      // (4096, 256)
    float* __restrict__ out)          // (4096, 256)
{
    __shared__ float4 sT[NII * 32];   // 28 KB folded coefficient tile

    const int tile = blockIdx.y;
    const int row0 = blockIdx.x * ROWS_PER_BLOCK;
    const int tid  = threadIdx.x;
    const int lane = tid & 31;
    const int wrp  = tid >> 5;        // 0..15
    const int f    = tile * 32 + lane;

    // Prefetch X (independent of smem prologue -> DRAM latency hidden)
    float xv[4];
    #pragma unroll
    for (int it = 0; it < 4; ++it)
        xv[it] = X[(row0 + it * 16 + wrp) * NF + f];

    // Copy folded table tile (L2 resident after K1): 28 KB, LDG.128/STS.128
    #pragma unroll
    for (int idx = tid; idx < NII * 32; idx += K2_THREADS)
        sT[idx] = g_tab[tile * (NII * 32) + idx];
    __syncthreads();

    #pragma unroll
    for (int it = 0; it < 4; ++it) {
        const float xs = xv[it] * 55.0f;
        int ii = (int)xs;             // x >= 0 -> trunc == floor
        ii = min(ii, 54);
        const float u = xs - (float)ii;
        // conflict-free LDS.128: ii stride = 512 B (multiple of 32 banks)
        const float4 c = sT[ii * 32 + lane];
        out[(row0 + it * 16 + wrp) * NF + f] =
            fmaf(fmaf(fmaf(c.w, u, c.z), u, c.y), u, c.x);
    }
}

extern "C" void kernel_launch(void* const* d_in, const int* in_sizes, int n_in,
                              void* d_out, int out_size) {
    const float* x    = (const float*)d_in[0];   // (4096, 256)
    const float* ctrl = (const float*)d_in[1];   // (64, 256)
    const float* bias = (const float*)d_in[2];   // (256,)
    float* out = (float*)d_out;

    PTab T;
    make_ptab(T);   // host double math, knot-only, deterministic

    BSL_fold<<<NII, 256>>>(T, ctrl, bias);

    dim3 grid(NBATCH / ROWS_PER_BLOCK, NF / 32);   // (64, 8) = 512 blocks
    BSL_25898652795515_kernel<<<grid, K2_THREADS>>>(x, out);
}